// round 2
// baseline (speedup 1.0000x reference)
#include <cuda_runtime.h>

// HGAN triplet loss, restructured + packed f32x2 FMA (FFMA2, PTX-only path):
//   score[b] = b_fc + sum_k num_k/den_k,
//   num_k = sum_{n,m} exp(S_k[n,m]) * F_k[n,m],  den_k = sum_{n,m} exp(S_k[n,m])
//   S_k[n,m] = sum_h W_att[k,h] * Aa[b,h,n] * Ac[b,h,m]   (b_att cancels in softmax)
//   F_k[n,m] = sum_h W_fc[k*H+h] * Aa[b,h,n] * Ac[b,h,m]  (fc folded into aggregation)
//   loss = mean_b relu(score_neg - score_pos + 0.2)        (b_fc cancels)
// The (S,F) pair is accumulated as one packed f32x2 per point -> 2 MAC/instr.

#define B_ 32
#define N_ 256
#define E_ 300
#define H_ 256
#define K_ 8

typedef unsigned long long u64;

__device__ __forceinline__ void fma2(u64& acc, u64 a, u64 c) {
    asm("fma.rn.f32x2 %0, %1, %2, %0;" : "+l"(acc) : "l"(a), "l"(c));
}
__device__ __forceinline__ void unpack2(u64 v, float& lo, float& hi) {
    asm("mov.b64 {%0, %1}, %2;" : "=f"(lo), "=f"(hi) : "l"(v));
}

// Scratch (device globals: allocation-free per harness rules)
__device__ float g_proj[3][B_][H_][N_];   // 0: anchor@W_a2h, 1: pos@W_c2h, 2: neg@W_c2h
__device__ float g_num[2][B_][K_];
__device__ float g_den[2][B_][K_];

// ---------------------------------------------------------------------------
// Projection: g_proj[which][b][h][n] = bias[h] + sum_e X[b][n][e] * W[h][e]
// 64x64 tile per block, E chunked by 20. W duplicated as (w,w) pairs so the
// inner product runs on packed f32x2 (8 FFMA2 per e-step = 16 MAC).
// ---------------------------------------------------------------------------
__global__ __launch_bounds__(256)
void proj_kernel(const float* __restrict__ X, const float* __restrict__ W,
                 const float* __restrict__ bias, int which) {
    const int b  = blockIdx.z;
    const int h0 = blockIdx.y * 64;
    const int n0 = blockIdx.x * 64;
    const int tid = threadIdx.x;
    const int tx = tid & 15, ty = tid >> 4;

    __shared__ float2 Ws[20][64];  // (w,w) duplicated, [e][h]
    __shared__ float  Xs[20][68];  // [e][n], padded (row = 272B, 16B-aligned)

    u64 acc[4][2];
    #pragma unroll
    for (int i = 0; i < 4; i++) { acc[i][0] = 0ull; acc[i][1] = 0ull; }

    const float* Xb = X + (size_t)b * N_ * E_;

    for (int e0 = 0; e0 < E_; e0 += 20) {
        #pragma unroll
        for (int l = 0; l < 5; l++) {
            int idx = tid + l * 256;         // 0..1279 = 64 rows x 20 cols
            int rl = idx / 20;
            int el = idx - rl * 20;
            float w = W[(h0 + rl) * E_ + e0 + el];
            Ws[el][rl] = make_float2(w, w);
            Xs[el][rl] = Xb[(n0 + rl) * E_ + e0 + el];
        }
        __syncthreads();
        #pragma unroll
        for (int e = 0; e < 20; e++) {
            ulonglong2 w01 = *(const ulonglong2*)&Ws[e][ty * 4];
            ulonglong2 w23 = *(const ulonglong2*)&Ws[e][ty * 4 + 2];
            ulonglong2 xp  = *(const ulonglong2*)&Xs[e][tx * 4];  // 2 x (x,x+1) pairs
            u64 wv[4] = {w01.x, w01.y, w23.x, w23.y};
            u64 xv[2] = {xp.x, xp.y};
            #pragma unroll
            for (int i = 0; i < 4; i++) {
                fma2(acc[i][0], wv[i], xv[0]);
                fma2(acc[i][1], wv[i], xv[1]);
            }
        }
        __syncthreads();
    }

    #pragma unroll
    for (int i = 0; i < 4; i++) {
        int h = h0 + ty * 4 + i;
        float bb = bias[h];
        float o0, o1, o2, o3;
        unpack2(acc[i][0], o0, o1);
        unpack2(acc[i][1], o2, o3);
        float4 o = make_float4(o0 + bb, o1 + bb, o2 + bb, o3 + bb);
        *(float4*)&g_proj[which][b][h][n0 + tx * 4] = o;
    }
}

// ---------------------------------------------------------------------------
// Score: one block per (k, b, side). The (S,F) dual GEMM runs fully packed:
// A12s holds (watt*Aa, wfc*Aa) pairs, Cs holds (Ac, Ac) pairs, accumulators
// are packed (S,F) -> one fma.rn.f32x2 per (n,m,h) point.
// ---------------------------------------------------------------------------
__global__ __launch_bounds__(256, 3)
void score_kernel(const float* __restrict__ W_att, const float* __restrict__ W_fc) {
    const int k = blockIdx.x, b = blockIdx.y, side = blockIdx.z;
    const float* __restrict__ Aa = &g_proj[0][b][0][0];
    const float* __restrict__ Ac = &g_proj[1 + side][b][0][0];

    __shared__ float watt_s[H_], wfc_s[H_];
    __shared__ float2 A12s[16][64];   // (watt*Aa, wfc*Aa)
    __shared__ float2 Cs  [16][64];   // (Ac, Ac)
    __shared__ float rn[8], rd[8];

    const int tid = threadIdx.x;
    const int tx = tid & 15, ty = tid >> 4;
    const int lc = tid & 63, lr = tid >> 6;

    for (int h = tid; h < H_; h += 256) {
        watt_s[h] = W_att[k * H_ + h];
        wfc_s[h]  = W_fc [k * H_ + h];
    }

    float num = 0.f, den = 0.f;

    for (int nt = 0; nt < 4; nt++) {
      for (int mt = 0; mt < 4; mt++) {
        const int n0 = nt * 64, m0 = mt * 64;
        u64 acc[4][4];
        #pragma unroll
        for (int i = 0; i < 4; i++)
            #pragma unroll
            for (int j = 0; j < 4; j++) acc[i][j] = 0ull;

        for (int h0 = 0; h0 < H_; h0 += 16) {
            __syncthreads();   // also covers watt_s/wfc_s on the first pass
            #pragma unroll
            for (int i = 0; i < 4; i++) {
                int hh = h0 + lr + i * 4;
                float av = Aa[hh * N_ + n0 + lc];
                A12s[lr + i * 4][lc] = make_float2(watt_s[hh] * av, wfc_s[hh] * av);
                float cv = Ac[hh * N_ + m0 + lc];
                Cs  [lr + i * 4][lc] = make_float2(cv, cv);
            }
            __syncthreads();
            #pragma unroll
            for (int hh = 0; hh < 16; hh++) {
                ulonglong2 a01 = *(const ulonglong2*)&A12s[hh][ty * 4];
                ulonglong2 a23 = *(const ulonglong2*)&A12s[hh][ty * 4 + 2];
                ulonglong2 c01 = *(const ulonglong2*)&Cs  [hh][tx * 4];
                ulonglong2 c23 = *(const ulonglong2*)&Cs  [hh][tx * 4 + 2];
                u64 a[4] = {a01.x, a01.y, a23.x, a23.y};
                u64 c[4] = {c01.x, c01.y, c23.x, c23.y};
                #pragma unroll
                for (int i = 0; i < 4; i++)
                    #pragma unroll
                    for (int j = 0; j < 4; j++)
                        fma2(acc[i][j], a[i], c[j]);
            }
        }

        // logits are O(0.2 std) -> exp without max-subtraction is safe
        #pragma unroll
        for (int i = 0; i < 4; i++)
            #pragma unroll
            for (int j = 0; j < 4; j++) {
                float S, F;
                unpack2(acc[i][j], S, F);
                float e = __expf(S);
                den += e;
                num = fmaf(e, F, num);
            }
      }
    }

    // block reduction
    #pragma unroll
    for (int o = 16; o; o >>= 1) {
        num += __shfl_down_sync(0xffffffffu, num, o);
        den += __shfl_down_sync(0xffffffffu, den, o);
    }
    const int wid = tid >> 5, lane = tid & 31;
    if (lane == 0) { rn[wid] = num; rd[wid] = den; }
    __syncthreads();
    if (tid == 0) {
        float sn = 0.f, sd = 0.f;
        #pragma unroll
        for (int w = 0; w < 8; w++) { sn += rn[w]; sd += rd[w]; }
        g_num[side][b][k] = sn;
        g_den[side][b][k] = sd;
    }
}

// ---------------------------------------------------------------------------
// Finalize: loss = mean_b relu(score_n - score_p + margin). b_fc cancels.
// ---------------------------------------------------------------------------
__global__ void finalize_kernel(float* __restrict__ out) {
    const int b = threadIdx.x;  // 32 threads
    float sp = 0.f, sn = 0.f;
    #pragma unroll
    for (int k = 0; k < K_; k++) {
        sp += g_num[0][b][k] / g_den[0][b][k];
        sn += g_num[1][b][k] / g_den[1][b][k];
    }
    float v = fmaxf(sn - sp + 0.2f, 0.f);
    #pragma unroll
    for (int o = 16; o; o >>= 1) v += __shfl_down_sync(0xffffffffu, v, o);
    if (b == 0) out[0] = v * (1.0f / B_);
}

// ---------------------------------------------------------------------------
extern "C" void kernel_launch(void* const* d_in, const int* in_sizes, int n_in,
                              void* d_out, int out_size) {
    const float* he_anchor = (const float*)d_in[0];
    const float* he_pos    = (const float*)d_in[1];
    const float* he_neg    = (const float*)d_in[2];
    const float* W_a2h     = (const float*)d_in[3];
    const float* b_a2h     = (const float*)d_in[4];
    const float* W_c2h     = (const float*)d_in[5];
    const float* b_c2h     = (const float*)d_in[6];
    const float* W_att     = (const float*)d_in[7];
    // d_in[8] = b_att  : cancels in per-(b,k) softmax -> unused
    const float* W_fc      = (const float*)d_in[9];
    // d_in[10] = b_fc  : cancels in score_n - score_p -> unused

    dim3 pgrid(4, 4, B_);
    proj_kernel<<<pgrid, 256>>>(he_anchor, W_a2h, b_a2h, 0);
    proj_kernel<<<pgrid, 256>>>(he_pos,    W_c2h, b_c2h, 1);
    proj_kernel<<<pgrid, 256>>>(he_neg,    W_c2h, b_c2h, 2);

    score_kernel<<<dim3(K_, B_, 2), 256>>>(W_att, W_fc);

    finalize_kernel<<<1, 32>>>((float*)d_out);
}

// round 4
// speedup vs baseline: 2.7555x; 2.7555x over previous
#include <cuda_runtime.h>
#include <cuda_bf16.h>
#include <cstdint>

// HGAN triplet loss:
//   score[b] = b_fc + sum_k num_k/den_k       (b_att cancels in softmax,
//   num_k = sum_{n,m} exp(S_k[n,m])*F_k[n,m],  b_fc cancels in score diff)
//   S_k[n,m] = sum_h W_att[k,h]*Aa[h,n]*Ac[h,m]
//   F_k[n,m] = sum_h W_fc [k,h]*Aa[h,n]*Ac[h,m]
// Score GEMMs run on HMMA (mma.sync m16n8k16 bf16, fp32 acc) with hi/lo bf16
// splitting (3 passes) for fp32-class accuracy. tcgen05 is unavailable at the
// harness's compute_103 PTX target; mma.sync is baseline ISA.

#define B_ 32
#define N_ 256
#define E_ 300
#define H_ 256
#define K_ 8

// ---------------------------------------------------------------------------
// Device scratch (allocation-free per harness rules)
// ---------------------------------------------------------------------------
__device__ float    g_projT[3][B_][N_][H_];          // transposed: [n][h], 24 MB
__device__ uint32_t g_Cpk[B_][2][2][256][128];       // [b][side][hi/lo][m][h/2], 16 MB
__device__ float    g_num[2][B_][K_];
__device__ float    g_den[2][B_][K_];

// ---------------------------------------------------------------------------
// Helpers
// ---------------------------------------------------------------------------
__device__ __forceinline__ uint32_t smem_u32(const void* p) {
    uint32_t a;
    asm("{ .reg .u64 t; cvta.to.shared.u64 t, %1; cvt.u32.u64 %0, t; }" : "=r"(a) : "l"(p));
    return a;
}
// pack (v0 -> low half, v1 -> high half) as bf16x2
__device__ __forceinline__ uint32_t cvt2(float v0, float v1) {
    uint32_t r;
    asm("cvt.rn.bf16x2.f32 %0, %1, %2;" : "=r"(r) : "f"(v1), "f"(v0));
    return r;
}
// hi/lo bf16 split of a pair of fp32 values
__device__ __forceinline__ void split2(float v0, float v1, uint32_t& uhi, uint32_t& ulo) {
    uhi = cvt2(v0, v1);
    float f0 = __uint_as_float(uhi << 16);
    float f1 = __uint_as_float(uhi & 0xffff0000u);
    ulo = cvt2(v0 - f0, v1 - f1);
}
__device__ __forceinline__ void ldsm4(uint32_t* r, uint32_t addr) {
    asm volatile("ldmatrix.sync.aligned.m8n8.x4.shared.b16 {%0,%1,%2,%3}, [%4];"
        : "=r"(r[0]), "=r"(r[1]), "=r"(r[2]), "=r"(r[3]) : "r"(addr));
}
__device__ __forceinline__ void mma_bf16(float* d, const uint32_t* a,
                                         uint32_t b0, uint32_t b1) {
    asm volatile("mma.sync.aligned.m16n8k16.row.col.f32.bf16.bf16.f32 "
        "{%0,%1,%2,%3}, {%4,%5,%6,%7}, {%8,%9}, {%0,%1,%2,%3};"
        : "+f"(d[0]), "+f"(d[1]), "+f"(d[2]), "+f"(d[3])
        : "r"(a[0]), "r"(a[1]), "r"(a[2]), "r"(a[3]), "r"(b0), "r"(b1));
}

// ---------------------------------------------------------------------------
// Projection: g_projT[which][b][n][h] = bias[h] + sum_e X[b][n][e]*W[h][e]
// (R1 kernel, output transposed to [n][h] so score fills need no transpose)
// ---------------------------------------------------------------------------
__global__ __launch_bounds__(256)
void proj_kernel(const float* __restrict__ X, const float* __restrict__ W,
                 const float* __restrict__ bias, int which) {
    const int b  = blockIdx.z;
    const int h0 = blockIdx.y * 64;
    const int n0 = blockIdx.x * 64;
    const int tid = threadIdx.x;
    const int tx = tid & 15, ty = tid >> 4;

    __shared__ float Ws[20][68];
    __shared__ float Xs[20][68];

    float acc[4][4] = {};
    const float* Xb = X + (size_t)b * N_ * E_;

    for (int e0 = 0; e0 < E_; e0 += 20) {
        #pragma unroll
        for (int l = 0; l < 5; l++) {
            int idx = tid + l * 256;
            int rl = idx / 20;
            int el = idx - rl * 20;
            Ws[el][rl] = W [(h0 + rl) * E_ + e0 + el];
            Xs[el][rl] = Xb[(n0 + rl) * E_ + e0 + el];
        }
        __syncthreads();
        #pragma unroll
        for (int e = 0; e < 20; e++) {
            float4 wv4 = *(const float4*)&Ws[e][ty * 4];
            float4 xv4 = *(const float4*)&Xs[e][tx * 4];
            float wv[4] = {wv4.x, wv4.y, wv4.z, wv4.w};
            float xv[4] = {xv4.x, xv4.y, xv4.z, xv4.w};
            #pragma unroll
            for (int i = 0; i < 4; i++)
                #pragma unroll
                for (int j = 0; j < 4; j++)
                    acc[i][j] = fmaf(wv[i], xv[j], acc[i][j]);
        }
        __syncthreads();
    }

    float bb0 = bias[h0 + ty * 4 + 0];
    float bb1 = bias[h0 + ty * 4 + 1];
    float bb2 = bias[h0 + ty * 4 + 2];
    float bb3 = bias[h0 + ty * 4 + 3];
    #pragma unroll
    for (int j = 0; j < 4; j++) {
        int n = n0 + tx * 4 + j;
        float4 o = make_float4(acc[0][j] + bb0, acc[1][j] + bb1,
                               acc[2][j] + bb2, acc[3][j] + bb3);
        *(float4*)&g_projT[which][b][n][h0 + ty * 4] = o;
    }
}

// ---------------------------------------------------------------------------
// C-pack: hi/lo bf16 split of Ac (k-independent), layout [m][h] packed pairs.
// ---------------------------------------------------------------------------
__global__ __launch_bounds__(256)
void cpack_kernel() {
    const int b = blockIdx.x, side = blockIdx.y;
    const float* src = &g_projT[1 + side][b][0][0];
    for (int p = threadIdx.x; p < 256 * 128; p += 256) {
        int m = p >> 7, hp = p & 127;
        float2 v = *(const float2*)(src + m * H_ + hp * 2);
        uint32_t hi, lo;
        split2(v.x, v.y, hi, lo);
        g_Cpk[b][side][0][m][hp] = hi;
        g_Cpk[b][side][1][m][hp] = lo;
    }
}

// ---------------------------------------------------------------------------
// Score: CTA per (k, b, side). Output tiles 64n x 128m; h streamed in chunks
// of 32. A operand scaled by watt/wfc and hi/lo-split in-kernel; C operand
// copied from the global pack. Warp w: n-rows 16*(w&3), m-cols 64*(w>>2).
// Per k16 step / m32 half: 24 HMMA (S: hi*hi+lo*hi+hi*lo, F: same).
// ---------------------------------------------------------------------------
#define ASTR 20   // u32 stride per smem row (40 bf16 = 80 B, conflict-free)

__global__ __launch_bounds__(256, 2)
void score_kernel(const float* __restrict__ W_att, const float* __restrict__ W_fc) {
    __shared__ float watt_s[H_], wfc_s[H_];
    __shared__ uint32_t AShi[64 * ASTR], ASlo[64 * ASTR];
    __shared__ uint32_t AFhi[64 * ASTR], AFlo[64 * ASTR];
    __shared__ uint32_t Chi [128 * ASTR], Clo[128 * ASTR];
    __shared__ float rn[8], rd[8];

    const int tid  = threadIdx.x;
    const int lane = tid & 31, w = tid >> 5;
    const int k = blockIdx.x, b = blockIdx.y, side = blockIdx.z;

    for (int h = tid; h < H_; h += 256) {
        watt_s[h] = W_att[k * H_ + h];
        wfc_s[h]  = W_fc [k * H_ + h];
    }

    const float*    At = &g_projT[0][b][0][0];
    const uint32_t* Cp = &g_Cpk[b][side][0][0][0];

    const uint32_t aShb = smem_u32(AShi), aSlb = smem_u32(ASlo);
    const uint32_t aFhb = smem_u32(AFhi), aFlb = smem_u32(AFlo);
    const uint32_t cHb  = smem_u32(Chi),  cLb  = smem_u32(Clo);

    // fill-index precompute
    const int fa_n = tid >> 2, fa_i4 = (tid & 3) * 8;
    const int fc_var = tid >> 7, fc_m = tid & 127;
    uint32_t* fc_dst = (fc_var ? Clo : Chi) + fc_m * ASTR;

    // compute-index precompute
    const int wn0 = 16 * (w & 3), wm0 = 64 * (w >> 2);
    const uint32_t a_off = ((uint32_t)(wn0 + (lane & 15)) * ASTR * 4) + ((lane >> 4) << 4);
    const uint32_t c_row = (lane & 7) + ((lane >> 4) << 3);
    const uint32_t c_off = c_row * ASTR * 4 + (((lane >> 3) & 1) << 4);

    float num = 0.f, den = 0.f;

    for (int nt = 0; nt < 4; nt++) {
      for (int mt = 0; mt < 2; mt++) {
        float accS[2][4][4], accF[2][4][4];
        #pragma unroll
        for (int mh = 0; mh < 2; mh++)
            #pragma unroll
            for (int g = 0; g < 4; g++)
                #pragma unroll
                for (int r = 0; r < 4; r++) { accS[mh][g][r] = 0.f; accF[mh][g][r] = 0.f; }

        for (int hc = 0; hc < 8; hc++) {
            const int h0 = hc * 32;
            __syncthreads();   // previous chunk's compute done

            // ---- A fill: 64n x 32h, scaled + split (8 h-values per thread)
            {
                const float* src = At + (nt * 64 + fa_n) * H_ + h0 + fa_i4;
                float4 v0 = *(const float4*)src;
                float4 v1 = *(const float4*)(src + 4);
                float4 a0 = *(const float4*)(watt_s + h0 + fa_i4);
                float4 a1 = *(const float4*)(watt_s + h0 + fa_i4 + 4);
                float4 f0 = *(const float4*)(wfc_s  + h0 + fa_i4);
                float4 f1 = *(const float4*)(wfc_s  + h0 + fa_i4 + 4);
                const int bi = fa_n * ASTR + (fa_i4 >> 1);
                uint32_t hi, lo;
                split2(a0.x * v0.x, a0.y * v0.y, hi, lo); AShi[bi + 0] = hi; ASlo[bi + 0] = lo;
                split2(a0.z * v0.z, a0.w * v0.w, hi, lo); AShi[bi + 1] = hi; ASlo[bi + 1] = lo;
                split2(a1.x * v1.x, a1.y * v1.y, hi, lo); AShi[bi + 2] = hi; ASlo[bi + 2] = lo;
                split2(a1.z * v1.z, a1.w * v1.w, hi, lo); AShi[bi + 3] = hi; ASlo[bi + 3] = lo;
                split2(f0.x * v0.x, f0.y * v0.y, hi, lo); AFhi[bi + 0] = hi; AFlo[bi + 0] = lo;
                split2(f0.z * v0.z, f0.w * v0.w, hi, lo); AFhi[bi + 1] = hi; AFlo[bi + 1] = lo;
                split2(f1.x * v1.x, f1.y * v1.y, hi, lo); AFhi[bi + 2] = hi; AFlo[bi + 2] = lo;
                split2(f1.z * v1.z, f1.w * v1.w, hi, lo); AFhi[bi + 3] = hi; AFlo[bi + 3] = lo;
            }
            // ---- C fill: copy packed hi/lo rows (16 u32 per thread)
            {
                const uint32_t* s = Cp + (fc_var * 256 + mt * 128 + fc_m) * 128 + (h0 >> 1);
                uint4 q0 = *(const uint4*)(s + 0);
                uint4 q1 = *(const uint4*)(s + 4);
                uint4 q2 = *(const uint4*)(s + 8);
                uint4 q3 = *(const uint4*)(s + 12);
                *(uint4*)(fc_dst + 0)  = q0;
                *(uint4*)(fc_dst + 4)  = q1;
                *(uint4*)(fc_dst + 8)  = q2;
                *(uint4*)(fc_dst + 12) = q3;
            }
            __syncthreads();   // fill visible

            // ---- HMMA compute
            #pragma unroll
            for (int ks = 0; ks < 2; ks++) {
                const uint32_t hkb = (uint32_t)(ks * 32);   // 16 bf16 = 32 bytes
                uint32_t aSh[4], aSl[4], aFh[4], aFl[4];
                ldsm4(aSh, aShb + a_off + hkb);
                ldsm4(aSl, aSlb + a_off + hkb);
                ldsm4(aFh, aFhb + a_off + hkb);
                ldsm4(aFl, aFlb + a_off + hkb);
                #pragma unroll
                for (int mh = 0; mh < 2; mh++) {
                    const uint32_t mrow = (uint32_t)(wm0 + mh * 32) * ASTR * 4;
                    uint32_t c[8];
                    ldsm4(c + 0, cHb + mrow + c_off + hkb);
                    ldsm4(c + 4, cHb + mrow + 16 * ASTR * 4 + c_off + hkb);
                    #pragma unroll
                    for (int g = 0; g < 4; g++) {
                        mma_bf16(accS[mh][g], aSh, c[2*g], c[2*g+1]);
                        mma_bf16(accS[mh][g], aSl, c[2*g], c[2*g+1]);
                        mma_bf16(accF[mh][g], aFh, c[2*g], c[2*g+1]);
                        mma_bf16(accF[mh][g], aFl, c[2*g], c[2*g+1]);
                    }
                    ldsm4(c + 0, cLb + mrow + c_off + hkb);
                    ldsm4(c + 4, cLb + mrow + 16 * ASTR * 4 + c_off + hkb);
                    #pragma unroll
                    for (int g = 0; g < 4; g++) {
                        mma_bf16(accS[mh][g], aSh, c[2*g], c[2*g+1]);
                        mma_bf16(accF[mh][g], aFh, c[2*g], c[2*g+1]);
                    }
                }
            }
        }

        // ---- epilogue for this tile: exp + local reduce (logits O(0.2): safe)
        #pragma unroll
        for (int mh = 0; mh < 2; mh++)
            #pragma unroll
            for (int g = 0; g < 4; g++)
                #pragma unroll
                for (int r = 0; r < 4; r++) {
                    float e = __expf(accS[mh][g][r]);
                    den += e;
                    num = fmaf(e, accF[mh][g][r], num);
                }
      }
    }

    // block reduction
    #pragma unroll
    for (int o = 16; o; o >>= 1) {
        num += __shfl_down_sync(0xffffffffu, num, o);
        den += __shfl_down_sync(0xffffffffu, den, o);
    }
    if (lane == 0) { rn[w] = num; rd[w] = den; }
    __syncthreads();
    if (tid == 0) {
        float sn = 0.f, sd = 0.f;
        #pragma unroll
        for (int q = 0; q < 8; q++) { sn += rn[q]; sd += rd[q]; }
        g_num[side][b][k] = sn;
        g_den[side][b][k] = sd;
    }
}

// ---------------------------------------------------------------------------
// Finalize: loss = mean_b relu(score_n - score_p + margin).
// ---------------------------------------------------------------------------
__global__ void finalize_kernel(float* __restrict__ out) {
    const int b = threadIdx.x;  // 32 threads
    float sp = 0.f, sn = 0.f;
    #pragma unroll
    for (int k = 0; k < K_; k++) {
        sp += g_num[0][b][k] / g_den[0][b][k];
        sn += g_num[1][b][k] / g_den[1][b][k];
    }
    float v = fmaxf(sn - sp + 0.2f, 0.f);
    #pragma unroll
    for (int o = 16; o; o >>= 1) v += __shfl_down_sync(0xffffffffu, v, o);
    if (b == 0) out[0] = v * (1.0f / B_);
}

// ---------------------------------------------------------------------------
extern "C" void kernel_launch(void* const* d_in, const int* in_sizes, int n_in,
                              void* d_out, int out_size) {
    const float* he_anchor = (const float*)d_in[0];
    const float* he_pos    = (const float*)d_in[1];
    const float* he_neg    = (const float*)d_in[2];
    const float* W_a2h     = (const float*)d_in[3];
    const float* b_a2h     = (const float*)d_in[4];
    const float* W_c2h     = (const float*)d_in[5];
    const float* b_c2h     = (const float*)d_in[6];
    const float* W_att     = (const float*)d_in[7];
    // d_in[8] = b_att : cancels in softmax
    const float* W_fc      = (const float*)d_in[9];
    // d_in[10] = b_fc : cancels in score difference

    dim3 pgrid(4, 4, B_);
    proj_kernel<<<pgrid, 256>>>(he_anchor, W_a2h, b_a2h, 0);
    proj_kernel<<<pgrid, 256>>>(he_pos,    W_c2h, b_c2h, 1);
    proj_kernel<<<pgrid, 256>>>(he_neg,    W_c2h, b_c2h, 2);

    cpack_kernel<<<dim3(B_, 2), 256>>>();

    score_kernel<<<dim3(K_, B_, 2), 256>>>(W_att, W_fc);

    finalize_kernel<<<1, 32>>>((float*)d_out);
}